// round 8
// baseline (speedup 1.0000x reference)
#include <cuda_runtime.h>
#include <stdint.h>

// Problem shape (fixed by the dataset)
#define M_DIM 1024
#define K_DIM 2048
#define N_DIM 2048

// Tiling: 64 x 32 output tile per CTA, 128 threads (4 warps).
// Each warp: 16 m-rows x 32 n-lanes, acc[16] per thread.
// A codes: warp-uniform LDG.128 straight from GMEM (1 line -> 1 wavefront).
// W codes: staged in smem in KT=128 chunks, double-buffered (16 barriers).
#define BM 64
#define BN 32
#define KT 128
#define NT (K_DIM / KT)        // 16 k-chunks

#define SW_STRIDE 144          // 128 data + 16 pad; /16 = 9 odd -> LDS.128 min phases
#define SW_BUF (BN * SW_STRIDE)          // 4608 B

#define SMEM_BYTES (65536 + 2 * SW_BUF)  // 74752 -> occ 3

// Scratch: quantized codes (allocation-free __device__ globals)
__device__ uint8_t g_A8[M_DIM * K_DIM];
__device__ uint8_t g_W8[N_DIM * K_DIM];
__device__ uint8_t g_LUT8[65536];

static __device__ __forceinline__ uint8_t clamp_u8(float v) {
    int c = (int)v;
    c = c < 0 ? 0 : (c > 255 ? 255 : c);
    return (uint8_t)c;
}

__global__ void quantA_kernel(const float* __restrict__ src) {
    int i = blockIdx.x * blockDim.x + threadIdx.x;   // groups of 4
    if (i < M_DIM * K_DIM / 4) {
        float4 v = ((const float4*)src)[i];
        uchar4 b;
        b.x = clamp_u8(v.x); b.y = clamp_u8(v.y);
        b.z = clamp_u8(v.z); b.w = clamp_u8(v.w);
        ((uchar4*)g_A8)[i] = b;
    }
}

__global__ void quantW_kernel(const float* __restrict__ src) {
    int i = blockIdx.x * blockDim.x + threadIdx.x;
    if (i < N_DIM * K_DIM / 4) {
        float4 v = ((const float4*)src)[i];
        uchar4 b;
        b.x = clamp_u8(v.x); b.y = clamp_u8(v.y);
        b.z = clamp_u8(v.z); b.w = clamp_u8(v.w);
        ((uchar4*)g_W8)[i] = b;
    }
}

__global__ void quantLUT_kernel(const int* __restrict__ lut) {
    int i = blockIdx.x * blockDim.x + threadIdx.x;   // groups of 4
    if (i < 65536 / 4) {
        int4 v = ((const int4*)lut)[i];
        uchar4 b;
        b.x = (uint8_t)v.x; b.y = (uint8_t)v.y;
        b.z = (uint8_t)v.z; b.w = (uint8_t)v.w;
        ((uchar4*)g_LUT8)[i] = b;
    }
}

// Index build: ((aword shift)&0xFF00)|w  -> SHF+LOP3 per index.
#define GATHER4(accv, aword, wv0, wv1, wv2, wv3)             \
    do {                                                     \
        uint32_t _i0 = (((aword) << 8)  & 0xFF00u) | (wv0);  \
        uint32_t _i1 = (( aword)        & 0xFF00u) | (wv1);  \
        uint32_t _i2 = (((aword) >> 8)  & 0xFF00u) | (wv2);  \
        uint32_t _i3 = (((aword) >> 16) & 0xFF00u) | (wv3);  \
        accv += sLUT[_i0];                                   \
        accv += sLUT[_i1];                                   \
        accv += sLUT[_i2];                                   \
        accv += sLUT[_i3];                                   \
    } while (0)

// One k-group of 8: a codes from two broadcast words, w codes from two words.
#define KGROUP8(alo, ahi, wlo, whi, accv)                                  \
    do {                                                                   \
        uint32_t _w0 =  (wlo)        & 255u, _w1 = ((wlo) >> 8)  & 255u;   \
        uint32_t _w2 = ((wlo) >> 16) & 255u, _w3 =  (wlo) >> 24;           \
        uint32_t _w4 =  (whi)        & 255u, _w5 = ((whi) >> 8)  & 255u;   \
        uint32_t _w6 = ((whi) >> 16) & 255u, _w7 =  (whi) >> 24;           \
        GATHER4(accv, alo, _w0, _w1, _w2, _w3);                            \
        GATHER4(accv, ahi, _w4, _w5, _w6, _w7);                            \
    } while (0)

// Main LUT-GEMM kernel.
// Grid: 1024 CTAs (16 m-tiles x 64 n-tiles), 128 threads, occ 3 -> 12 warps/SM.
__global__ void __launch_bounds__(128, 3)
lut_gemm_kernel(const float* __restrict__ bias,
                float* __restrict__ out) {
    extern __shared__ uint8_t smem[];
    uint8_t* sLUT = smem;                     // 65536 B
    uint8_t* sW   = smem + 65536;             // [2][BN][SW_STRIDE]

    const int tid  = threadIdx.x;
    const int lane = tid & 31;
    const int warp = tid >> 5;                // 0..3 -> m-group of 16 rows

    // Copy pre-quantized LUT (64KB) into shared with 16B vector loads.
    for (int i = tid; i < 65536 / 16; i += 128) {
        ((uint4*)sLUT)[i] = ((const uint4*)g_LUT8)[i];
    }

    const int tileId = blockIdx.x;
    const int m0 = (tileId >> 6) * BM;        // 16 tile rows
    const int n0 = (tileId & 63) * BN;        // 64 tile cols

    const int mBase = warp * 16;              // warp's first row within tile
    const int nLane = n0 + lane;              // this lane's output column

    int acc[16];
#pragma unroll
    for (int i = 0; i < 16; i++) acc[i] = 0;

    // W staging: thread t covers row (t>>2), 32B chunk ((t&3)*32).
    // Consecutive tids read consecutive 32B of the same row -> coalesced LDG,
    // 16B-aligned STS (SW_STRIDE=144).
    const int wrow = tid >> 2;
    const int woff = (tid & 3) * 32;
    const uint8_t* gWst = g_W8 + ((size_t)(n0 + wrow)) * K_DIM + woff;
    uint8_t*       sWst = sW + wrow * SW_STRIDE + woff;

    // A codes: warp-uniform rows, read straight from GMEM.
    const uint8_t* gAw = g_A8 + (size_t)(m0 + mBase) * K_DIM;

    const uint8_t* sWrow = sW + lane * SW_STRIDE;   // 16B-aligned per lane

    // ---- prologue: stage W chunk 0 into buffer 0 ----
    {
        uint4 w0 = *(const uint4*)(gWst);
        uint4 w1 = *(const uint4*)(gWst + 16);
        *(uint4*)(sWst)      = w0;
        *(uint4*)(sWst + 16) = w1;
    }
    __syncthreads();

    for (int t = 0; t < NT; t++) {
        // Prefetch W chunk t+1 into registers (clamped on last iter).
        const int kn = ((t + 1 < NT) ? (t + 1) : t) * KT;
        uint4 rw0 = *(const uint4*)(gWst + kn);
        uint4 rw1 = *(const uint4*)(gWst + kn + 16);

        const uint8_t* sWbuf = sWrow + (t & 1) * SW_BUF;
        const int kbase = t * KT;

        // 4 sub-slices of 32 k each.
#pragma unroll
        for (int kk = 0; kk < 4; kk++) {
            // Per-lane w codes for this 32-k slice: 2x LDS.128 (4 phases each).
            const uint8_t* wp = sWbuf + kk * 32;
            uint4 wv0 = *(const uint4*)(wp);        // k 0..15
            uint4 wv1 = *(const uint4*)(wp + 16);   // k 16..31

            const uint8_t* ap0 = gAw + kbase + kk * 32;
#pragma unroll
            for (int m = 0; m < 16; m++) {
                // Warp-uniform a codes: one LDG.128 (single 128B line -> 1 wf).
                uint4 av = *(const uint4*)(ap0 + (size_t)m * K_DIM);
                KGROUP8(av.x, av.y, wv0.x, wv0.y, acc[m]);
                KGROUP8(av.z, av.w, wv0.z, wv0.w, acc[m]);
                // second 16B of the slice are in the same 32B; split across
                // two 16B words: av covers k 0..15, need k 16..31 too:
                uint4 av2 = *(const uint4*)(ap0 + (size_t)m * K_DIM + 16);
                KGROUP8(av2.x, av2.y, wv1.x, wv1.y, acc[m]);
                KGROUP8(av2.z, av2.w, wv1.z, wv1.w, acc[m]);
            }
        }

        // Stage W chunk t+1 into the other buffer, then sync.
        const int nb = (t + 1) & 1;
        *(uint4*)(sWst + nb * SW_BUF)      = rw0;
        *(uint4*)(sWst + nb * SW_BUF + 16) = rw1;
        __syncthreads();
    }

    const float b = bias[nLane];
#pragma unroll
    for (int m = 0; m < 16; m++) {
        out[(size_t)(m0 + mBase + m) * N_DIM + nLane] = (float)acc[m] + b;
    }
}

extern "C" void kernel_launch(void* const* d_in, const int* in_sizes, int n_in,
                              void* d_out, int out_size) {
    const float* input  = (const float*)d_in[0];  // [M, K] codes as f32
    const float* weight = (const float*)d_in[1];  // [N, K] codes as f32
    const float* bias   = (const float*)d_in[2];  // [N]
    const int*   lut    = (const int*)d_in[3];    // [256*256]
    float* out = (float*)d_out;

    (void)in_sizes; (void)n_in; (void)out_size;

    // Opt-in to >48KB dynamic smem (idempotent; capture-safe)
    cudaFuncSetAttribute((const void*)lut_gemm_kernel,
                         cudaFuncAttributeMaxDynamicSharedMemorySize, SMEM_BYTES);

    quantA_kernel<<<(M_DIM * K_DIM / 4 + 255) / 256, 256>>>(input);
    quantW_kernel<<<(N_DIM * K_DIM / 4 + 255) / 256, 256>>>(weight);
    quantLUT_kernel<<<(65536 / 4 + 255) / 256, 256>>>(lut);

    dim3 grid(1024);  // 16 x 64 tiles of 64 x 32
    lut_gemm_kernel<<<grid, 128, SMEM_BYTES>>>(bias, out);
}

// round 9
// speedup vs baseline: 1.0556x; 1.0556x over previous
#include <cuda_runtime.h>
#include <stdint.h>

// Problem shape (fixed by the dataset)
#define M_DIM 1024
#define K_DIM 2048
#define N_DIM 2048

// Tiling: 64 x 32 output tile, 128 threads (4 warps).
// Each warp: 16 m-rows x 32 n-lanes, acc[16] per thread.
// KT=32 k-slice; A and W tiles double-buffered in smem (R5 compute body).
// Persistent CTAs pull tiles from a global atomic queue.
#define BM 64
#define BN 32
#define KT 32
#define NT (K_DIM / KT)        // 64 k-tiles
#define NUM_TILES 1024         // 16 m-tiles x 64 n-tiles
#define PERSIST_CTAS 456       // 3 per SM on 152 SMs

#define SA_STRIDE 32           // dense: broadcast reads don't conflict
#define SA_BUF (BM * SA_STRIDE)          // 2048 B
#define SW_STRIDE 80           // 16B-aligned, 80/16=5 odd -> LDS.128 4-phase min
#define SW_BUF (BN * SW_STRIDE)          // 2560 B

#define SMEM_BYTES (65536 + 2 * SA_BUF + 2 * SW_BUF)   // 74752 -> occ 3

// Scratch (allocation-free __device__ globals)
__device__ uint8_t g_A8[M_DIM * K_DIM];
__device__ uint8_t g_W8[N_DIM * K_DIM];
__device__ uint8_t g_LUT8[65536];
__device__ unsigned int g_tileCtr;

static __device__ __forceinline__ uint8_t clamp_u8(float v) {
    int c = (int)v;
    c = c < 0 ? 0 : (c > 255 ? 255 : c);
    return (uint8_t)c;
}

__global__ void quantA_kernel(const float* __restrict__ src) {
    int i = blockIdx.x * blockDim.x + threadIdx.x;   // groups of 4
    if (i < M_DIM * K_DIM / 4) {
        float4 v = ((const float4*)src)[i];
        uchar4 b;
        b.x = clamp_u8(v.x); b.y = clamp_u8(v.y);
        b.z = clamp_u8(v.z); b.w = clamp_u8(v.w);
        ((uchar4*)g_A8)[i] = b;
    }
}

__global__ void quantW_kernel(const float* __restrict__ src) {
    int i = blockIdx.x * blockDim.x + threadIdx.x;
    if (i < N_DIM * K_DIM / 4) {
        float4 v = ((const float4*)src)[i];
        uchar4 b;
        b.x = clamp_u8(v.x); b.y = clamp_u8(v.y);
        b.z = clamp_u8(v.z); b.w = clamp_u8(v.w);
        ((uchar4*)g_W8)[i] = b;
    }
}

__global__ void quantLUT_kernel(const int* __restrict__ lut) {
    int i = blockIdx.x * blockDim.x + threadIdx.x;   // groups of 4
    if (i == 0) g_tileCtr = 0;                       // reset queue every launch
    if (i < 65536 / 4) {
        int4 v = ((const int4*)lut)[i];
        uchar4 b;
        b.x = (uint8_t)v.x; b.y = (uint8_t)v.y;
        b.z = (uint8_t)v.z; b.w = (uint8_t)v.w;
        ((uchar4*)g_LUT8)[i] = b;
    }
}

// Index build: ((aword shift)&0xFF00)|w  -> SHF+LOP3 per index.
#define GATHER4(accv, aword, wv0, wv1, wv2, wv3)             \
    do {                                                     \
        uint32_t _i0 = (((aword) << 8)  & 0xFF00u) | (wv0);  \
        uint32_t _i1 = (( aword)        & 0xFF00u) | (wv1);  \
        uint32_t _i2 = (((aword) >> 8)  & 0xFF00u) | (wv2);  \
        uint32_t _i3 = (((aword) >> 16) & 0xFF00u) | (wv3);  \
        accv += sLUT[_i0];                                   \
        accv += sLUT[_i1];                                   \
        accv += sLUT[_i2];                                   \
        accv += sLUT[_i3];                                   \
    } while (0)

// One k-group of 8: a codes from two broadcast words, w codes from two words.
#define KGROUP8(alo, ahi, wlo, whi, accv)                                  \
    do {                                                                   \
        uint32_t _w0 =  (wlo)        & 255u, _w1 = ((wlo) >> 8)  & 255u;   \
        uint32_t _w2 = ((wlo) >> 16) & 255u, _w3 =  (wlo) >> 24;           \
        uint32_t _w4 =  (whi)        & 255u, _w5 = ((whi) >> 8)  & 255u;   \
        uint32_t _w6 = ((whi) >> 16) & 255u, _w7 =  (whi) >> 24;           \
        GATHER4(accv, alo, _w0, _w1, _w2, _w3);                            \
        GATHER4(accv, ahi, _w4, _w5, _w6, _w7);                            \
    } while (0)

// Persistent LUT-GEMM kernel: 456 CTAs, 128 threads, occ 3 -> 12 warps/SM.
__global__ void __launch_bounds__(128, 3)
lut_gemm_kernel(const float* __restrict__ bias,
                float* __restrict__ out) {
    extern __shared__ uint8_t smem[];
    uint8_t* sLUT = smem;                     // 65536 B
    uint8_t* sA   = smem + 65536;             // [2][BM][SA_STRIDE]
    uint8_t* sW   = sA + 2 * SA_BUF;          // [2][BN][SW_STRIDE]
    __shared__ int sTile;

    const int tid  = threadIdx.x;
    const int lane = tid & 31;
    const int warp = tid >> 5;                // 0..3 -> m-group of 16 rows

    // Copy pre-quantized LUT (64KB) into shared ONCE per persistent CTA.
    for (int i = tid; i < 65536 / 16; i += 128) {
        ((uint4*)sLUT)[i] = ((const uint4*)g_LUT8)[i];
    }

    const int mBase = warp * 16;              // warp's first row within tile

    // Per-thread staging roles (tile-independent parts)
    const int arow   = tid >> 1;
    const int achunk = (tid & 1) * 16;
    uint8_t* sAst = sA + arow * SA_STRIDE + achunk;
    const int wrow   = tid >> 1;              // valid for tid < 64
    const int wchunk = (tid & 1) * 16;
    uint8_t* sWst = sW + wrow * SW_STRIDE + wchunk;

    const uint8_t* sArow = sA + mBase * SA_STRIDE;
    const uint8_t* sWrow = sW + lane * SW_STRIDE;   // 16B-aligned per lane

    for (;;) {
        if (tid == 0) sTile = (int)atomicAdd(&g_tileCtr, 1u);
        __syncthreads();                      // broadcast tile; also fences smem reuse
        const int tileId = sTile;
        if (tileId >= NUM_TILES) break;       // uniform exit

        const int m0 = (tileId >> 6) * BM;    // 16 tile rows
        const int n0 = (tileId & 63) * BN;    // 64 tile cols
        const int nLane = n0 + lane;          // this lane's output column

        int acc[16];
#pragma unroll
        for (int i = 0; i < 16; i++) acc[i] = 0;

        const uint8_t* gAst = g_A8 + ((size_t)(m0 + arow)) * K_DIM + achunk;
        const uint8_t* gWst = g_W8 + ((size_t)(n0 + wrow)) * K_DIM + wchunk;

        // ---- prologue: stage tile 0 into buffer 0 ----
        {
            uint4 ra = *(const uint4*)gAst;
            *(uint4*)sAst = ra;
            if (tid < 64) {
                uint4 rw = *(const uint4*)gWst;
                *(uint4*)sWst = rw;
            }
        }
        __syncthreads();

        for (int t = 0; t < NT; t++) {
            // Prefetch tile t+1 into registers (clamped on last iter).
            const int kn = ((t + 1 < NT) ? (t + 1) : t) * KT;
            uint4 ra_n = *(const uint4*)(gAst + kn);
            uint4 rw_n;
            if (tid < 64) rw_n = *(const uint4*)(gWst + kn);

            const int bufo = (t & 1);
            const uint8_t* sAbuf = sArow + bufo * SA_BUF;
            const uint8_t* sWbuf = sWrow + bufo * SW_BUF;

            // Per-lane w codes for this 32-k slice: 2x LDS.128 (4 phases, floor).
            uint4 wv0 = *(const uint4*)(sWbuf);        // k 0..15
            uint4 wv1 = *(const uint4*)(sWbuf + 16);   // k 16..31

            // Compute tile t: 16 m-rows x 32 k. A codes via broadcast LDS.64.
#pragma unroll
            for (int m = 0; m < 16; m++) {
                const uint8_t* ap = sAbuf + m * SA_STRIDE;
                uint2 a01 = *(const uint2*)(ap);        // k 0..7
                uint2 a23 = *(const uint2*)(ap + 8);    // k 8..15
                uint2 a45 = *(const uint2*)(ap + 16);   // k 16..23
                uint2 a67 = *(const uint2*)(ap + 24);   // k 24..31
                KGROUP8(a01.x, a01.y, wv0.x, wv0.y, acc[m]);
                KGROUP8(a23.x, a23.y, wv0.z, wv0.w, acc[m]);
                KGROUP8(a45.x, a45.y, wv1.x, wv1.y, acc[m]);
                KGROUP8(a67.x, a67.y, wv1.z, wv1.w, acc[m]);
            }

            // Stage tile t+1 into the other buffer, then sync.
            const int nbufo = ((t + 1) & 1);
            *(uint4*)(sAst + nbufo * SA_BUF) = ra_n;
            if (tid < 64) *(uint4*)(sWst + nbufo * SW_BUF) = rw_n;
            __syncthreads();
        }

        const float b = bias[nLane];
#pragma unroll
        for (int m = 0; m < 16; m++) {
            out[(size_t)(m0 + mBase + m) * N_DIM + nLane] = (float)acc[m] + b;
        }
        // loop back: the atomic-broadcast __syncthreads fences buffer reuse
    }
}

extern "C" void kernel_launch(void* const* d_in, const int* in_sizes, int n_in,
                              void* d_out, int out_size) {
    const float* input  = (const float*)d_in[0];  // [M, K] codes as f32
    const float* weight = (const float*)d_in[1];  // [N, K] codes as f32
    const float* bias   = (const float*)d_in[2];  // [N]
    const int*   lut    = (const int*)d_in[3];    // [256*256]
    float* out = (float*)d_out;

    (void)in_sizes; (void)n_in; (void)out_size;

    // Opt-in to >48KB dynamic smem (idempotent; capture-safe)
    cudaFuncSetAttribute((const void*)lut_gemm_kernel,
                         cudaFuncAttributeMaxDynamicSharedMemorySize, SMEM_BYTES);

    quantA_kernel<<<(M_DIM * K_DIM / 4 + 255) / 256, 256>>>(input);
    quantW_kernel<<<(N_DIM * K_DIM / 4 + 255) / 256, 256>>>(weight);
    quantLUT_kernel<<<(65536 / 4 + 255) / 256, 256>>>(lut);  // also resets queue

    lut_gemm_kernel<<<PERSIST_CTAS, 128, SMEM_BYTES>>>(bias, out);
}

// round 11
// speedup vs baseline: 1.0754x; 1.0188x over previous
#include <cuda_runtime.h>
#include <stdint.h>

// Problem shape (fixed by the dataset)
#define M_DIM 1024
#define K_DIM 2048
#define N_DIM 2048

// Tiling: 32 x 64 output tile per CTA, 128 threads (4 warps).
// Each warp: 8 m-rows x 64 n-cols (lane owns n and n+32) -> accA[8]+accB[8].
// Each A-code broadcast now feeds 8 lookups (4 k x 2 n) instead of 4.
#define BM 32
#define BN 64
#define KT 32
#define NT (K_DIM / KT)        // 64 k-tiles
#define NUM_TILES 1024         // 32 m-tiles x 32 n-tiles
#define PERSIST_CTAS 456       // 3 per SM on 152 SMs

#define SA_STRIDE 32           // dense; broadcast reads
#define SA_BUF (BM * SA_STRIDE)          // 1024 B
#define SW_STRIDE 48           // 32 data + 16 pad; /16=3 odd -> LDS.128 min phases
#define SW_BUF (BN * SW_STRIDE)          // 3072 B

#define SMEM_BYTES (65536 + 2 * SA_BUF + 2 * SW_BUF)   // 73728 -> occ 3

// Scratch (allocation-free __device__ globals)
__device__ uint8_t g_A8[M_DIM * K_DIM];
__device__ uint8_t g_W8[N_DIM * K_DIM];
__device__ uint8_t g_LUT8[65536];
__device__ unsigned int g_tileCtr;

static __device__ __forceinline__ uint8_t clamp_u8(float v) {
    int c = (int)v;
    c = c < 0 ? 0 : (c > 255 ? 255 : c);
    return (uint8_t)c;
}

__global__ void quantA_kernel(const float* __restrict__ src) {
    int i = blockIdx.x * blockDim.x + threadIdx.x;   // groups of 4
    if (i < M_DIM * K_DIM / 4) {
        float4 v = ((const float4*)src)[i];
        uchar4 b;
        b.x = clamp_u8(v.x); b.y = clamp_u8(v.y);
        b.z = clamp_u8(v.z); b.w = clamp_u8(v.w);
        ((uchar4*)g_A8)[i] = b;
    }
}

__global__ void quantW_kernel(const float* __restrict__ src) {
    int i = blockIdx.x * blockDim.x + threadIdx.x;
    if (i < N_DIM * K_DIM / 4) {
        float4 v = ((const float4*)src)[i];
        uchar4 b;
        b.x = clamp_u8(v.x); b.y = clamp_u8(v.y);
        b.z = clamp_u8(v.z); b.w = clamp_u8(v.w);
        ((uchar4*)g_W8)[i] = b;
    }
}

__global__ void quantLUT_kernel(const int* __restrict__ lut) {
    int i = blockIdx.x * blockDim.x + threadIdx.x;   // groups of 4
    if (i == 0) g_tileCtr = 0;                       // reset queue every launch
    if (i < 65536 / 4) {
        int4 v = ((const int4*)lut)[i];
        uchar4 b;
        b.x = (uint8_t)v.x; b.y = (uint8_t)v.y;
        b.z = (uint8_t)v.z; b.w = (uint8_t)v.w;
        ((uchar4*)g_LUT8)[i] = b;
    }
}

// Index build: ((aword shift)&0xFF00)|w  -> SHF+LOP3 per index.
#define GATHER4(accv, aword, wv0, wv1, wv2, wv3)             \
    do {                                                     \
        uint32_t _i0 = (((aword) << 8)  & 0xFF00u) | (wv0);  \
        uint32_t _i1 = (( aword)        & 0xFF00u) | (wv1);  \
        uint32_t _i2 = (((aword) >> 8)  & 0xFF00u) | (wv2);  \
        uint32_t _i3 = (((aword) >> 16) & 0xFF00u) | (wv3);  \
        accv += sLUT[_i0];                                   \
        accv += sLUT[_i1];                                   \
        accv += sLUT[_i2];                                   \
        accv += sLUT[_i3];                                   \
    } while (0)

// One k-group of 8: a codes from two broadcast words, w codes from two words.
#define KGROUP8(alo, ahi, wlo, whi, accv)                                  \
    do {                                                                   \
        uint32_t _w0 =  (wlo)        & 255u, _w1 = ((wlo) >> 8)  & 255u;   \
        uint32_t _w2 = ((wlo) >> 16) & 255u, _w3 =  (wlo) >> 24;           \
        uint32_t _w4 =  (whi)        & 255u, _w5 = ((whi) >> 8)  & 255u;   \
        uint32_t _w6 = ((whi) >> 16) & 255u, _w7 =  (whi) >> 24;           \
        GATHER4(accv, alo, _w0, _w1, _w2, _w3);                            \
        GATHER4(accv, ahi, _w4, _w5, _w6, _w7);                            \
    } while (0)

// Persistent LUT-GEMM kernel: 456 CTAs, 128 threads, occ 3 -> 12 warps/SM.
__global__ void __launch_bounds__(128, 3)
lut_gemm_kernel(const float* __restrict__ bias,
                float* __restrict__ out) {
    extern __shared__ uint8_t smem[];
    uint8_t* sLUT = smem;                     // 65536 B
    uint8_t* sA   = smem + 65536;             // [2][BM][SA_STRIDE]
    uint8_t* sW   = sA + 2 * SA_BUF;          // [2][BN][SW_STRIDE]
    __shared__ int sTile;

    const int tid  = threadIdx.x;
    const int lane = tid & 31;
    const int warp = tid >> 5;                // 0..3 -> m-group of 8 rows

    // Copy pre-quantized LUT (64KB) into shared ONCE per persistent CTA.
    for (int i = tid; i < 65536 / 16; i += 128) {
        ((uint4*)sLUT)[i] = ((const uint4*)g_LUT8)[i];
    }

    const int mBase = warp * 8;               // warp's first row within tile

    // Staging roles:
    // A: threads 0..63 cover 32 rows x 2 chunks of 16B.
    const int arow   = tid >> 1;
    const int achunk = (tid & 1) * 16;
    uint8_t* sAst = sA + arow * SA_STRIDE + achunk;
    // W: all 128 threads cover 64 rows x 2 chunks of 16B.
    const int wrow   = tid >> 1;
    const int wchunk = (tid & 1) * 16;
    uint8_t* sWst = sW + wrow * SW_STRIDE + wchunk;

    const uint8_t* sArow  = sA + mBase * SA_STRIDE;
    const uint8_t* sWrowA = sW + lane * SW_STRIDE;          // n = n0+lane
    const uint8_t* sWrowB = sW + (lane + 32) * SW_STRIDE;   // n = n0+lane+32

    for (;;) {
        if (tid == 0) sTile = (int)atomicAdd(&g_tileCtr, 1u);
        __syncthreads();                      // broadcast tile; fences smem reuse
        const int tileId = sTile;
        if (tileId >= NUM_TILES) break;       // uniform exit

        const int m0 = (tileId >> 5) * BM;    // 32 tile rows
        const int n0 = (tileId & 31) * BN;    // 32 tile cols

        int accA[8], accB[8];
#pragma unroll
        for (int i = 0; i < 8; i++) { accA[i] = 0; accB[i] = 0; }

        const uint8_t* gAst = g_A8 + ((size_t)(m0 + arow)) * K_DIM + achunk;
        const uint8_t* gWst = g_W8 + ((size_t)(n0 + wrow)) * K_DIM + wchunk;

        // ---- prologue: stage tile 0 into buffer 0 ----
        {
            if (tid < 64) {
                uint4 ra = *(const uint4*)gAst;
                *(uint4*)sAst = ra;
            }
            uint4 rw = *(const uint4*)gWst;
            *(uint4*)sWst = rw;
        }
        __syncthreads();

        for (int t = 0; t < NT; t++) {
            // Prefetch tile t+1 into registers (clamped on last iter).
            const int kn = ((t + 1 < NT) ? (t + 1) : t) * KT;
            uint4 ra_n;
            if (tid < 64) ra_n = *(const uint4*)(gAst + kn);
            uint4 rw_n = *(const uint4*)(gWst + kn);

            const int bufo = (t & 1);
            const uint8_t* sAbuf  = sArow  + bufo * SA_BUF;
            const uint8_t* sWbufA = sWrowA + bufo * SW_BUF;
            const uint8_t* sWbufB = sWrowB + bufo * SW_BUF;

            // Two 16-k halves: keeps live W regs at 8 (wa + wb).
#pragma unroll
            for (int h = 0; h < 2; h++) {
                uint4 wa = *(const uint4*)(sWbufA + h * 16);   // n,    16 k
                uint4 wb = *(const uint4*)(sWbufB + h * 16);   // n+32, 16 k

#pragma unroll
                for (int m = 0; m < 8; m++) {
                    const uint8_t* ap = sAbuf + m * SA_STRIDE + h * 16;
                    uint2 a01 = *(const uint2*)(ap);       // k 0..7 of half
                    uint2 a23 = *(const uint2*)(ap + 8);   // k 8..15 of half
                    // Each aword drives BOTH n-columns: broadcast amortized 2x.
                    KGROUP8(a01.x, a01.y, wa.x, wa.y, accA[m]);
                    KGROUP8(a23.x, a23.y, wa.z, wa.w, accA[m]);
                    KGROUP8(a01.x, a01.y, wb.x, wb.y, accB[m]);
                    KGROUP8(a23.x, a23.y, wb.z, wb.w, accB[m]);
                }
            }

            // Stage tile t+1 into the other buffer, then sync.
            const int nbufo = ((t + 1) & 1);
            if (tid < 64) *(uint4*)(sAst + nbufo * SA_BUF) = ra_n;
            *(uint4*)(sWst + nbufo * SW_BUF) = rw_n;
            __syncthreads();
        }

        const float bA = bias[n0 + lane];
        const float bB = bias[n0 + 32 + lane];
#pragma unroll
        for (int m = 0; m < 8; m++) {
            const size_t row = (size_t)(m0 + mBase + m) * N_DIM;
            out[row + n0 + lane]      = (float)accA[m] + bA;
            out[row + n0 + 32 + lane] = (float)accB[m] + bB;
        }
        // loop back: the atomic-broadcast __syncthreads fences buffer reuse
    }
}

extern "C" void kernel_launch(void* const* d_in, const int* in_sizes, int n_in,
                              void* d_out, int out_size) {
    const float* input  = (const float*)d_in[0];  // [M, K] codes as f32
    const float* weight = (const float*)d_in[1];  // [N, K] codes as f32
    const float* bias   = (const float*)d_in[2];  // [N]
    const int*   lut    = (const int*)d_in[3];    // [256*256]
    float* out = (float*)d_out;

    (void)in_sizes; (void)n_in; (void)out_size;

    // Opt-in to >48KB dynamic smem (idempotent; capture-safe)
    cudaFuncSetAttribute((const void*)lut_gemm_kernel,
                         cudaFuncAttributeMaxDynamicSharedMemorySize, SMEM_BYTES);

    quantA_kernel<<<(M_DIM * K_DIM / 4 + 255) / 256, 256>>>(input);
    quantW_kernel<<<(N_DIM * K_DIM / 4 + 255) / 256, 256>>>(weight);
    quantLUT_kernel<<<(65536 / 4 + 255) / 256, 256>>>(lut);  // also resets queue

    lut_gemm_kernel<<<PERSIST_CTAS, 128, SMEM_BYTES>>>(bias, out);
}

// round 12
// speedup vs baseline: 1.0779x; 1.0023x over previous
#include <cuda_runtime.h>
#include <stdint.h>

// Problem shape (fixed by the dataset)
#define M_DIM 1024
#define K_DIM 2048
#define N_DIM 2048

// Tiling: 32 x 64 output tile per CTA, 128 threads (4 warps).
// Each warp: 8 m-rows x 64 n-cols (lane owns n and n+32) -> accA[8]+accB[8].
// A codes: one LDS.128 broadcast per (m, 16k-half) -> feeds 32 lookups.
#define BM 32
#define BN 64
#define KT 32
#define NT (K_DIM / KT)        // 64 k-tiles
#define NUM_TILES 1024         // 32 m-tiles x 32 n-tiles
#define PERSIST_CTAS 456       // 3 per SM on 152 SMs

#define SA_STRIDE 32           // dense; broadcast reads
#define SA_BUF (BM * SA_STRIDE)          // 1024 B
#define SW_STRIDE 48           // 32 data + 16 pad; /16=3 odd -> LDS.128 min phases
#define SW_BUF (BN * SW_STRIDE)          // 3072 B

#define SMEM_BYTES (65536 + 2 * SA_BUF + 2 * SW_BUF)   // 73728 -> occ 3

// Scratch (allocation-free __device__ globals)
__device__ uint8_t g_A8[M_DIM * K_DIM];
__device__ uint8_t g_W8[N_DIM * K_DIM];
__device__ uint8_t g_LUT8[65536];
__device__ unsigned int g_tileCtr;

static __device__ __forceinline__ uint8_t clamp_u8(float v) {
    int c = (int)v;
    c = c < 0 ? 0 : (c > 255 ? 255 : c);
    return (uint8_t)c;
}

__global__ void quantA_kernel(const float* __restrict__ src) {
    int i = blockIdx.x * blockDim.x + threadIdx.x;   // groups of 4
    if (i < M_DIM * K_DIM / 4) {
        float4 v = ((const float4*)src)[i];
        uchar4 b;
        b.x = clamp_u8(v.x); b.y = clamp_u8(v.y);
        b.z = clamp_u8(v.z); b.w = clamp_u8(v.w);
        ((uchar4*)g_A8)[i] = b;
    }
}

__global__ void quantW_kernel(const float* __restrict__ src) {
    int i = blockIdx.x * blockDim.x + threadIdx.x;
    if (i < N_DIM * K_DIM / 4) {
        float4 v = ((const float4*)src)[i];
        uchar4 b;
        b.x = clamp_u8(v.x); b.y = clamp_u8(v.y);
        b.z = clamp_u8(v.z); b.w = clamp_u8(v.w);
        ((uchar4*)g_W8)[i] = b;
    }
}

__global__ void quantLUT_kernel(const int* __restrict__ lut) {
    int i = blockIdx.x * blockDim.x + threadIdx.x;   // groups of 4
    if (i == 0) g_tileCtr = 0;                       // reset queue every launch
    if (i < 65536 / 4) {
        int4 v = ((const int4*)lut)[i];
        uchar4 b;
        b.x = (uint8_t)v.x; b.y = (uint8_t)v.y;
        b.z = (uint8_t)v.z; b.w = (uint8_t)v.w;
        ((uchar4*)g_LUT8)[i] = b;
    }
}

// Index build: ((aword shift)&0xFF00)|w  -> SHF+LOP3 per index.
#define GATHER4(accv, aword, wv0, wv1, wv2, wv3)             \
    do {                                                     \
        uint32_t _i0 = (((aword) << 8)  & 0xFF00u) | (wv0);  \
        uint32_t _i1 = (( aword)        & 0xFF00u) | (wv1);  \
        uint32_t _i2 = (((aword) >> 8)  & 0xFF00u) | (wv2);  \
        uint32_t _i3 = (((aword) >> 16) & 0xFF00u) | (wv3);  \
        accv += sLUT[_i0];                                   \
        accv += sLUT[_i1];                                   \
        accv += sLUT[_i2];                                   \
        accv += sLUT[_i3];                                   \
    } while (0)

// One k-group of 8: a codes from two broadcast words, w codes from two words.
#define KGROUP8(alo, ahi, wlo, whi, accv)                                  \
    do {                                                                   \
        uint32_t _w0 =  (wlo)        & 255u, _w1 = ((wlo) >> 8)  & 255u;   \
        uint32_t _w2 = ((wlo) >> 16) & 255u, _w3 =  (wlo) >> 24;           \
        uint32_t _w4 =  (whi)        & 255u, _w5 = ((whi) >> 8)  & 255u;   \
        uint32_t _w6 = ((whi) >> 16) & 255u, _w7 =  (whi) >> 24;           \
        GATHER4(accv, alo, _w0, _w1, _w2, _w3);                            \
        GATHER4(accv, ahi, _w4, _w5, _w6, _w7);                            \
    } while (0)

// Persistent LUT-GEMM kernel: 456 CTAs, 128 threads, occ 3 -> 12 warps/SM.
__global__ void __launch_bounds__(128, 3)
lut_gemm_kernel(const float* __restrict__ bias,
                float* __restrict__ out) {
    extern __shared__ uint8_t smem[];
    uint8_t* sLUT = smem;                     // 65536 B
    uint8_t* sA   = smem + 65536;             // [2][BM][SA_STRIDE]
    uint8_t* sW   = sA + 2 * SA_BUF;          // [2][BN][SW_STRIDE]
    __shared__ int sTile;

    const int tid  = threadIdx.x;
    const int lane = tid & 31;
    const int warp = tid >> 5;                // 0..3 -> m-group of 8 rows

    // Copy pre-quantized LUT (64KB) into shared ONCE per persistent CTA.
    for (int i = tid; i < 65536 / 16; i += 128) {
        ((uint4*)sLUT)[i] = ((const uint4*)g_LUT8)[i];
    }

    const int mBase = warp * 8;               // warp's first row within tile

    // Staging roles:
    // A: threads 0..63 cover 32 rows x 2 chunks of 16B.
    const int arow   = tid >> 1;
    const int achunk = (tid & 1) * 16;
    uint8_t* sAst = sA + arow * SA_STRIDE + achunk;
    // W: all 128 threads cover 64 rows x 2 chunks of 16B.
    const int wrow   = tid >> 1;
    const int wchunk = (tid & 1) * 16;
    uint8_t* sWst = sW + wrow * SW_STRIDE + wchunk;

    const uint8_t* sArow  = sA + mBase * SA_STRIDE;
    const uint8_t* sWrowA = sW + lane * SW_STRIDE;          // n = n0+lane
    const uint8_t* sWrowB = sW + (lane + 32) * SW_STRIDE;   // n = n0+lane+32

    for (;;) {
        if (tid == 0) sTile = (int)atomicAdd(&g_tileCtr, 1u);
        __syncthreads();                      // broadcast tile; fences smem reuse
        const int tileId = sTile;
        if (tileId >= NUM_TILES) break;       // uniform exit

        const int m0 = (tileId >> 5) * BM;    // 32 tile rows
        const int n0 = (tileId & 31) * BN;    // 32 tile cols

        int accA[8], accB[8];
#pragma unroll
        for (int i = 0; i < 8; i++) { accA[i] = 0; accB[i] = 0; }

        const uint8_t* gAst = g_A8 + ((size_t)(m0 + arow)) * K_DIM + achunk;
        const uint8_t* gWst = g_W8 + ((size_t)(n0 + wrow)) * K_DIM + wchunk;

        // ---- prologue: stage tile 0 into buffer 0 ----
        {
            if (tid < 64) {
                uint4 ra = *(const uint4*)gAst;
                *(uint4*)sAst = ra;
            }
            uint4 rw = *(const uint4*)gWst;
            *(uint4*)sWst = rw;
        }
        __syncthreads();

        for (int t = 0; t < NT; t++) {
            // Prefetch tile t+1 into registers (clamped on last iter).
            const int kn = ((t + 1 < NT) ? (t + 1) : t) * KT;
            uint4 ra_n;
            if (tid < 64) ra_n = *(const uint4*)(gAst + kn);
            uint4 rw_n = *(const uint4*)(gWst + kn);

            const int bufo = (t & 1);
            const uint8_t* sAbuf  = sArow  + bufo * SA_BUF;
            const uint8_t* sWbufA = sWrowA + bufo * SW_BUF;
            const uint8_t* sWbufB = sWrowB + bufo * SW_BUF;

            // Two 16-k halves: keeps live W regs at 8 (wa + wb).
#pragma unroll
            for (int h = 0; h < 2; h++) {
                uint4 wa = *(const uint4*)(sWbufA + h * 16);   // n,    16 k
                uint4 wb = *(const uint4*)(sWbufB + h * 16);   // n+32, 16 k

#pragma unroll
                for (int m = 0; m < 8; m++) {
                    // One warp-uniform LDS.128 broadcast: 16 a-codes, feeds
                    // 32 lookups (16 k x 2 n-columns).
                    uint4 av = *(const uint4*)(sAbuf + m * SA_STRIDE + h * 16);
                    KGROUP8(av.x, av.y, wa.x, wa.y, accA[m]);
                    KGROUP8(av.z, av.w, wa.z, wa.w, accA[m]);
                    KGROUP8(av.x, av.y, wb.x, wb.y, accB[m]);
                    KGROUP8(av.z, av.w, wb.z, wb.w, accB[m]);
                }
            }

            // Stage tile t+1 into the other buffer, then sync.
            const int nbufo = ((t + 1) & 1);
            if (tid < 64) *(uint4*)(sAst + nbufo * SA_BUF) = ra_n;
            *(uint4*)(sWst + nbufo * SW_BUF) = rw_n;
            __syncthreads();
        }

        const float bA = bias[n0 + lane];
        const float bB = bias[n0 + 32 + lane];
#pragma unroll
        for (int m = 0; m < 8; m++) {
            const size_t row = (size_t)(m0 + mBase + m) * N_DIM;
            out[row + n0 + lane]      = (float)accA[m] + bA;
            out[row + n0 + 32 + lane] = (float)accB[m] + bB;
        }
        // loop back: the atomic-broadcast __syncthreads fences buffer reuse
    }
}

extern "C" void kernel_launch(void* const* d_in, const int* in_sizes, int n_in,
                              void* d_out, int out_size) {
    const float* input  = (const float*)d_in[0];  // [M, K] codes as f32
    const float* weight = (const float*)d_in[1];  // [N, K] codes as f32
    const float* bias   = (const float*)d_in[2];  // [N]
    const int*   lut    = (const int*)d_in[3];    // [256*256]
    float* out = (float*)d_out;

    (void)in_sizes; (void)n_in; (void)out_size;

    // Opt-in to >48KB dynamic smem (idempotent; capture-safe)
    cudaFuncSetAttribute((const void*)lut_gemm_kernel,
                         cudaFuncAttributeMaxDynamicSharedMemorySize, SMEM_BYTES);

    quantA_kernel<<<(M_DIM * K_DIM / 4 + 255) / 256, 256>>>(input);
    quantW_kernel<<<(N_DIM * K_DIM / 4 + 255) / 256, 256>>>(weight);
    quantLUT_kernel<<<(65536 / 4 + 255) / 256, 256>>>(lut);  // also resets queue

    lut_gemm_kernel<<<PERSIST_CTAS, 128, SMEM_BYTES>>>(bias, out);
}